// round 13
// baseline (speedup 1.0000x reference)
#include <cuda_runtime.h>
#include <cstdint>

// ---------------------------------------------------------------------------
// LightOnOCR patch merger: fused 2x2 unfold gather + Linear(4096->1024), TF32
// mma.sync. M=11955, N=1024, K=4096. CTA 128x128, 4 warps (64x64), K-chunk 32,
// 3-stage cp.async pipeline (2 CTAs/SM), XOR-swizzled smem, coalesced fills.
// Tail scheduling: first 592 tiles (2 exact waves) computed directly; last 160
// tiles split-K x8 into 1280 short items that backfill the wave tail, with a
// ticket-elected finisher CTA summing the 8 partials (fixed order -> determin.)
// ---------------------------------------------------------------------------

#define M_TOTAL 11955
#define STAGE_BYTES 32768            // A 16KB (128 rows x 128B) + B 16KB
#define SMEM_DYN (3 * STAGE_BYTES)   // 98304 B -> 2 CTAs/SM
#define FULL_TILES 592               // m_idx 0..73 (x8 n-tiles)
#define SPLIT_TILES 160              // m_idx 74..93
#define SPLIT_D 8                    // K split factor (512 per item)

static __device__ unsigned g_Wr[4u * 1024u * 1024u];             // [off][n][dd]
static __device__ float    g_part[(size_t)SPLIT_TILES * SPLIT_D * 16384u]; // 84MB
static __device__ int      g_ticket[SPLIT_TILES];                // zero-init; reset by finisher

// Image table (IMAGE_SIZES, PATCH=14, MERGE=2)
__constant__ int c_moff[7] = {0, 2420, 4620, 6060, 9085, 10525, 11955};
__constant__ int c_toff[6] = {0, 9680, 18480, 24240, 36340, 42100};
__constant__ int c_wm[6]   = {44, 55, 45, 55, 32, 55};
__constant__ int c_w[6]    = {88, 110, 90, 110, 64, 110};

__device__ __forceinline__ unsigned f2tf(float f) {
    unsigned u;
    asm("cvt.rna.tf32.f32 %0, %1;" : "=r"(u) : "f"(f));
    return u;
}
__device__ __forceinline__ uint32_t s2u(const void* p) {
    uint32_t a;
    asm("{ .reg .u64 t; cvta.to.shared.u64 t, %1; cvt.u32.u64 %0, t; }" : "=r"(a) : "l"(p));
    return a;
}
__device__ __forceinline__ void cp16(uint32_t dst, const void* src) {
    asm volatile("cp.async.cg.shared.global [%0], [%1], 16;" :: "r"(dst), "l"(src) : "memory");
}

// Weight reorder: [1024, 4096] -> g_Wr[off][n][dd], tf32-rounded (RNA).
__global__ void reorder_w_kernel(const float* __restrict__ w) {
    int id = blockIdx.x * 256 + threadIdx.x;
    int n = id >> 10, dd = id & 1023;
    float4 v = *reinterpret_cast<const float4*>(w + (size_t)n * 4096 + (dd << 2));
    g_Wr[0u * 1048576u + (n << 10) + dd] = f2tf(v.x);
    g_Wr[1u * 1048576u + (n << 10) + dd] = f2tf(v.y);
    g_Wr[2u * 1048576u + (n << 10) + dd] = f2tf(v.z);
    g_Wr[3u * 1048576u + (n << 10) + dd] = f2tf(v.w);
}

__global__ __launch_bounds__(128, 2) void merger_gemm(
    const float* __restrict__ feat, float* __restrict__ out)
{
    extern __shared__ char smem[];
    __shared__ int sTok[128], sWd[128];
    __shared__ int sOld;
    const int t = threadIdx.x, wid = t >> 5, lane = t & 31;

    // Work-item decode: bids [0,592) = full tiles (m_idx 0..73, n fast);
    // bids [592,1872) = split items: tl = sid>>3 (tile), kq = sid&7 (K eighth).
    int m_idx, n_idx, kt0, niter, tile_local;
    const int bid = blockIdx.x;
    const bool direct = bid < FULL_TILES;
    if (direct) {
        m_idx = bid >> 3; n_idx = bid & 7;
        kt0 = 0; niter = 128; tile_local = 0;
    } else {
        int sid = bid - FULL_TILES;
        tile_local = sid >> 3;
        m_idx = 74 + (tile_local >> 3); n_idx = tile_local & 7;
        int kq = sid & 7;
        kt0 = kq << 4; niter = 16;                   // 16 x 32-K chunks = K 512
    }
    const int m0 = m_idx << 7, n0 = n_idx << 7;

    // Row map: merged row (m0+i) -> (base token, patch width)
    {
        int r = m0 + t;
        if (r > M_TOTAL - 1) r = M_TOTAL - 1;        // clamp loads; stores guarded
        int img = 0;
        #pragma unroll
        for (int i = 1; i < 6; i++) img += (r >= c_moff[i]);
        int local = r - c_moff[img];
        int wm = c_wm[img];
        int br = local / wm, bc = local - br * wm;
        sTok[t] = c_toff[img] + (br << 1) * c_w[img] + (bc << 1);
        sWd[t]  = c_w[img];
    }
    __syncthreads();

    // Fill mapping: thread handles rows {16j + (t>>3)}, chunk c = t&7 (16B).
    const int rbase = t >> 3, c = t & 7;
    const uint32_t csw = (uint32_t)(c ^ (rbase & 7)) << 4;
    const uint32_t off0 = (uint32_t)rbase * 128 + csw;
    int tokA[8], wdA[8];
    const unsigned* pB[8];
    #pragma unroll
    for (int j = 0; j < 8; j++) {
        int row = (j << 4) + rbase;
        tokA[j] = sTok[row];
        wdA[j]  = sWd[row];
        pB[j]   = g_Wr + ((size_t)(n0 + row) << 10) + (c << 2);
    }
    const uint32_t sbase = s2u(smem);

    auto fill = [&](int kc) {
        const int s = kc % 3;
        const int koff = kc >> 5;
        const int dd0 = (kc & 31) << 5;
        const int kh = koff >> 1, kw = koff & 1;
        const uint32_t dA = sbase + s * STAGE_BYTES + off0;
        const size_t woff = ((size_t)koff << 20) + dd0;
        const size_t aoff = dd0 + (c << 2);
        #pragma unroll
        for (int j = 0; j < 8; j++) {
            int token = tokA[j] + kh * wdA[j] + kw;
            cp16(dA + (j << 11), feat + (size_t)token * 1024 + aoff);
            cp16(dA + 16384 + (j << 11), pB[j] + woff);
        }
        asm volatile("cp.async.commit_group;" ::: "memory");
    };

    const int tg = lane >> 2, t4 = lane & 3;
    const int wr = wid >> 1, wc = wid & 1;           // warp grid 2x2, 64x64 tiles

    float acc[4][8][4];
    #pragma unroll
    for (int mf = 0; mf < 4; mf++)
        #pragma unroll
        for (int nf = 0; nf < 8; nf++)
            #pragma unroll
            for (int i = 0; i < 4; i++) acc[mf][nf][i] = 0.0f;

    fill(kt0); fill(kt0 + 1);

    for (int it = 0; it < niter; it++) {
        const int kc = kt0 + it;
        if (it < niter - 1) asm volatile("cp.async.wait_group 1;" ::: "memory");
        else                asm volatile("cp.async.wait_group 0;" ::: "memory");
        __syncthreads();
        if (it + 2 < niter) fill(kc + 2);

        const unsigned* sA = reinterpret_cast<const unsigned*>(smem + (kc % 3) * STAGE_BYTES);
        const unsigned* sB = sA + 4096;
        #pragma unroll
        for (int ks = 0; ks < 4; ks++) {
            const int x0 = ((((ks << 1)    ) ^ tg) << 2) + t4;
            const int x1 = ((((ks << 1) + 1) ^ tg) << 2) + t4;
            unsigned a[4][4];
            #pragma unroll
            for (int mf = 0; mf < 4; mf++) {
                const int mrow = (wr << 6) + (mf << 4) + tg;
                const unsigned* p0 = sA + (mrow << 5);
                const unsigned* p8 = p0 + 256;
                a[mf][0] = p0[x0];                   // raw f32 bits -> HW tf32 trunc
                a[mf][1] = p8[x0];
                a[mf][2] = p0[x1];
                a[mf][3] = p8[x1];
            }
            #pragma unroll
            for (int nf = 0; nf < 8; nf++) {
                const int nrow = (wc << 6) + (nf << 3) + tg;
                const unsigned* q = sB + (nrow << 5);
                unsigned b0 = q[x0];
                unsigned b1 = q[x1];
                #pragma unroll
                for (int mf = 0; mf < 4; mf++) {
                    asm volatile(
                        "mma.sync.aligned.m16n8k8.row.col.f32.tf32.tf32.f32 "
                        "{%0,%1,%2,%3}, {%4,%5,%6,%7}, {%8,%9}, {%0,%1,%2,%3};"
                        : "+f"(acc[mf][nf][0]), "+f"(acc[mf][nf][1]),
                          "+f"(acc[mf][nf][2]), "+f"(acc[mf][nf][3])
                        : "r"(a[mf][0]), "r"(a[mf][1]), "r"(a[mf][2]), "r"(a[mf][3]),
                          "r"(b0), "r"(b1));
                }
            }
        }
    }

    if (direct) {
        // Direct epilogue (m_idx <= 73: all rows valid)
        #pragma unroll
        for (int mf = 0; mf < 4; mf++) {
            const int row0 = m0 + (wr << 6) + (mf << 4) + tg;
            #pragma unroll
            for (int nf = 0; nf < 8; nf++) {
                const int col = n0 + (wc << 6) + (nf << 3) + (t4 << 1);
                *reinterpret_cast<float2*>(out + (size_t)row0 * 1024 + col) =
                    make_float2(acc[mf][nf][0], acc[mf][nf][1]);
                *reinterpret_cast<float2*>(out + (size_t)(row0 + 8) * 1024 + col) =
                    make_float2(acc[mf][nf][2], acc[mf][nf][3]);
            }
        }
        return;
    }

    // Split item: write partial [128x128] then ticket; 8th arriver reduces.
    {
        int sid = bid - FULL_TILES;
        float* part = g_part + (size_t)sid * 16384u;
        #pragma unroll
        for (int mf = 0; mf < 4; mf++) {
            const int prow = (wr << 6) + (mf << 4) + tg;
            #pragma unroll
            for (int nf = 0; nf < 8; nf++) {
                const int pcol = (wc << 6) + (nf << 3) + (t4 << 1);
                *reinterpret_cast<float2*>(part + (prow << 7) + pcol) =
                    make_float2(acc[mf][nf][0], acc[mf][nf][1]);
                *reinterpret_cast<float2*>(part + ((prow + 8) << 7) + pcol) =
                    make_float2(acc[mf][nf][2], acc[mf][nf][3]);
            }
        }
        __threadfence();
        __syncthreads();
        if (t == 0) sOld = atomicAdd(&g_ticket[tile_local], 1);
        __syncthreads();
        if (sOld == SPLIT_D - 1) {
            __threadfence();   // acquire: see all 8 partials
            const float4* pp = reinterpret_cast<const float4*>(
                g_part + (size_t)tile_local * SPLIT_D * 16384u);
            for (int j = 0; j < 32; j++) {
                const int idx4 = (j << 7) + t;       // float4 index in tile (0..4095)
                float4 s = pp[idx4];
                #pragma unroll
                for (int q = 1; q < SPLIT_D; q++) {  // fixed order -> deterministic
                    float4 v = pp[q * 4096 + idx4];
                    s.x += v.x; s.y += v.y; s.z += v.z; s.w += v.w;
                }
                const int el = idx4 << 2;
                const int row = m0 + (el >> 7);
                if (row < M_TOTAL)
                    *reinterpret_cast<float4*>(out + (size_t)row * 1024 + n0 + (el & 127)) = s;
            }
            __threadfence();
            if (t == 0) g_ticket[tile_local] = 0;    // reset for next graph replay
        }
    }
}

extern "C" void kernel_launch(void* const* d_in, const int* in_sizes, int n_in,
                              void* d_out, int out_size)
{
    const float* feat   = (const float*)d_in[0];   // [47820, 1024] fp32
    const float* weight = (const float*)d_in[1];   // [1024, 4096] fp32
    float* out = (float*)d_out;                    // [11955, 1024] fp32
    (void)in_sizes; (void)n_in; (void)out_size;

    cudaFuncSetAttribute(merger_gemm, cudaFuncAttributeMaxDynamicSharedMemorySize, SMEM_DYN);
    reorder_w_kernel<<<4096, 256>>>(weight);
    merger_gemm<<<FULL_TILES + SPLIT_TILES * SPLIT_D, 128, SMEM_DYN>>>(feat, out);
}

// round 15
// speedup vs baseline: 2.2035x; 2.2035x over previous
#include <cuda_runtime.h>
#include <cuda_fp16.h>
#include <cstdint>

// ---------------------------------------------------------------------------
// LightOnOCR patch merger: fused 2x2 unfold gather + Linear(4096->1024).
// FP16 mma.sync (m16n8k16) with fp32 accumulation. M=11955, N=1024, K=4096.
// Pre-pass converts feat->fp16 (g_Af) and reorders weight->fp16 (g_Wh[off][n][dd]).
// GEMM: CTA 128x128, 4 warps (64x64), K-chunk 64 (128B rows), 3-stage cp.async
// pipeline (96KB smem -> 2 CTAs/SM), XOR-swizzled smem, coalesced fills.
// ---------------------------------------------------------------------------

#define M_TOTAL 11955
#define STAGE_BYTES 32768            // A 16KB (128 rows x 128B) + B 16KB
#define SMEM_DYN (3 * STAGE_BYTES)   // 98304 B -> 2 CTAs/SM

static __device__ __half g_Wh[4u * 1024u * 1024u];     // [off][n][dd] fp16, 8MB
static __device__ __half g_Af[47820u * 1024u];         // feat in fp16, 94MB

// Image table (IMAGE_SIZES, PATCH=14, MERGE=2)
__constant__ int c_moff[7] = {0, 2420, 4620, 6060, 9085, 10525, 11955};
__constant__ int c_toff[6] = {0, 9680, 18480, 24240, 36340, 42100};
__constant__ int c_wm[6]   = {44, 55, 45, 55, 32, 55};
__constant__ int c_w[6]    = {88, 110, 90, 110, 64, 110};

__device__ __forceinline__ uint32_t s2u(const void* p) {
    uint32_t a;
    asm("{ .reg .u64 t; cvta.to.shared.u64 t, %1; cvt.u32.u64 %0, t; }" : "=r"(a) : "l"(p));
    return a;
}
__device__ __forceinline__ void cp16(uint32_t dst, const void* src) {
    asm volatile("cp.async.cg.shared.global [%0], [%1], 16;" :: "r"(dst), "l"(src) : "memory");
}

// feat [47820,1024] f32 -> g_Af fp16 (RN). 8 floats per thread, exact cover.
__global__ void convert_feat_kernel(const float* __restrict__ f) {
    size_t base = ((size_t)blockIdx.x * 256 + threadIdx.x) * 8;   // 6120960*8 = 48967680
    float4 v0 = *reinterpret_cast<const float4*>(f + base);
    float4 v1 = *reinterpret_cast<const float4*>(f + base + 4);
    __half2 h[4];
    h[0] = __floats2half2_rn(v0.x, v0.y);
    h[1] = __floats2half2_rn(v0.z, v0.w);
    h[2] = __floats2half2_rn(v1.x, v1.y);
    h[3] = __floats2half2_rn(v1.z, v1.w);
    *reinterpret_cast<uint4*>(g_Af + base) = *reinterpret_cast<uint4*>(h);
}

// Weight reorder: [1024,4096] f32 -> g_Wh[off][n][dd] fp16 (RN).
__global__ void reorder_w_kernel(const float* __restrict__ w) {
    int id = blockIdx.x * 256 + threadIdx.x;
    int n = id >> 10, dd = id & 1023;
    float4 v = *reinterpret_cast<const float4*>(w + (size_t)n * 4096 + (dd << 2));
    g_Wh[0u * 1048576u + (n << 10) + dd] = __float2half_rn(v.x);
    g_Wh[1u * 1048576u + (n << 10) + dd] = __float2half_rn(v.y);
    g_Wh[2u * 1048576u + (n << 10) + dd] = __float2half_rn(v.z);
    g_Wh[3u * 1048576u + (n << 10) + dd] = __float2half_rn(v.w);
}

__global__ __launch_bounds__(128, 2) void merger_gemm(
    float* __restrict__ out)
{
    extern __shared__ char smem[];
    __shared__ int sTok[128], sWd[128];
    const int t = threadIdx.x, wid = t >> 5, lane = t & 31;
    const int m0 = blockIdx.y << 7, n0 = blockIdx.x << 7;

    // Row map: merged row (m0+i) -> (base token, patch width)
    {
        int r = m0 + t;
        if (r > M_TOTAL - 1) r = M_TOTAL - 1;        // clamp loads; stores guarded
        int img = 0;
        #pragma unroll
        for (int i = 1; i < 6; i++) img += (r >= c_moff[i]);
        int local = r - c_moff[img];
        int wm = c_wm[img];
        int br = local / wm, bc = local - br * wm;
        sTok[t] = c_toff[img] + (br << 1) * c_w[img] + (bc << 1);
        sWd[t]  = c_w[img];
    }
    __syncthreads();

    // Fill mapping: thread handles rows {16j + (t>>3)}, chunk c = t&7 (16B = 8 halves).
    // One warp covers 4 rows x 8 chunks = four full 128B lines (coalesced).
    const int rbase = t >> 3, c = t & 7;
    const uint32_t csw = (uint32_t)(c ^ (rbase & 7)) << 4;
    const uint32_t off0 = (uint32_t)rbase * 128 + csw;
    int tokA[8], wdA[8];
    const __half* pB[8];
    #pragma unroll
    for (int j = 0; j < 8; j++) {
        int row = (j << 4) + rbase;
        tokA[j] = sTok[row];
        wdA[j]  = sWd[row];
        pB[j]   = g_Wh + ((size_t)(n0 + row) << 10) + (c << 3);
    }
    const uint32_t sbase = s2u(smem);

    // K-chunk = 64 halves (128B/row). kc in [0,64): koff = kc>>4, dd0 = (kc&15)*64.
    auto fill = [&](int kc) {
        const int s = kc % 3;
        const int koff = kc >> 4;
        const int dd0 = (kc & 15) << 6;
        const int kh = koff >> 1, kw = koff & 1;
        const uint32_t dA = sbase + s * STAGE_BYTES + off0;
        const size_t woff = ((size_t)koff << 20) + dd0;
        const size_t aoff = dd0 + (c << 3);
        #pragma unroll
        for (int j = 0; j < 8; j++) {
            int token = tokA[j] + kh * wdA[j] + kw;
            cp16(dA + (j << 11), g_Af + (size_t)token * 1024 + aoff);
            cp16(dA + 16384 + (j << 11), pB[j] + woff);
        }
        asm volatile("cp.async.commit_group;" ::: "memory");
    };

    const int tg = lane >> 2, t4 = lane & 3;
    const int wr = wid >> 1, wc = wid & 1;           // warp grid 2x2, 64x64 tiles

    float acc[4][8][4];
    #pragma unroll
    for (int mf = 0; mf < 4; mf++)
        #pragma unroll
        for (int nf = 0; nf < 8; nf++)
            #pragma unroll
            for (int i = 0; i < 4; i++) acc[mf][nf][i] = 0.0f;

    fill(0); fill(1);

    for (int kt = 0; kt < 64; kt++) {
        if (kt < 63) asm volatile("cp.async.wait_group 1;" ::: "memory");
        else         asm volatile("cp.async.wait_group 0;" ::: "memory");
        __syncthreads();
        if (kt + 2 < 64) fill(kt + 2);

        const unsigned* sA = reinterpret_cast<const unsigned*>(smem + (kt % 3) * STAGE_BYTES);
        const unsigned* sB = sA + 4096;
        #pragma unroll
        for (int kk = 0; kk < 4; kk++) {             // 4 x k16 steps over K=64
            // word offsets: chunk (2kk [+1]) ^ tg, word t4 within chunk
            const int x0 = ((((kk << 1)    ) ^ tg) << 2) + t4;   // k halves 16kk+2t4,+1
            const int x1 = ((((kk << 1) + 1) ^ tg) << 2) + t4;   // k halves 16kk+8+2t4,+1
            unsigned a[4][4];
            #pragma unroll
            for (int mf = 0; mf < 4; mf++) {
                const int mrow = (wr << 6) + (mf << 4) + tg;
                const unsigned* p0 = sA + (mrow << 5);           // 32 words/row
                const unsigned* p8 = p0 + 256;                   // +8 rows
                a[mf][0] = p0[x0];   // (row tg,   k lo pair)
                a[mf][1] = p8[x0];   // (row tg+8, k lo pair)
                a[mf][2] = p0[x1];   // (row tg,   k hi pair)
                a[mf][3] = p8[x1];   // (row tg+8, k hi pair)
            }
            #pragma unroll
            for (int nf = 0; nf < 8; nf++) {
                const int nrow = (wc << 6) + (nf << 3) + tg;
                const unsigned* q = sB + (nrow << 5);
                unsigned b0 = q[x0];
                unsigned b1 = q[x1];
                #pragma unroll
                for (int mf = 0; mf < 4; mf++) {
                    asm volatile(
                        "mma.sync.aligned.m16n8k16.row.col.f32.f16.f16.f32 "
                        "{%0,%1,%2,%3}, {%4,%5,%6,%7}, {%8,%9}, {%0,%1,%2,%3};"
                        : "+f"(acc[mf][nf][0]), "+f"(acc[mf][nf][1]),
                          "+f"(acc[mf][nf][2]), "+f"(acc[mf][nf][3])
                        : "r"(a[mf][0]), "r"(a[mf][1]), "r"(a[mf][2]), "r"(a[mf][3]),
                          "r"(b0), "r"(b1));
                }
            }
        }
    }

    // Epilogue
    #pragma unroll
    for (int mf = 0; mf < 4; mf++) {
        const int row0 = m0 + (wr << 6) + (mf << 4) + tg;
        #pragma unroll
        for (int nf = 0; nf < 8; nf++) {
            const int col = n0 + (wc << 6) + (nf << 3) + (t4 << 1);
            if (row0 < M_TOTAL)
                *reinterpret_cast<float2*>(out + (size_t)row0 * 1024 + col) =
                    make_float2(acc[mf][nf][0], acc[mf][nf][1]);
            if (row0 + 8 < M_TOTAL)
                *reinterpret_cast<float2*>(out + (size_t)(row0 + 8) * 1024 + col) =
                    make_float2(acc[mf][nf][2], acc[mf][nf][3]);
        }
    }
}

extern "C" void kernel_launch(void* const* d_in, const int* in_sizes, int n_in,
                              void* d_out, int out_size)
{
    const float* feat   = (const float*)d_in[0];   // [47820, 1024] fp32
    const float* weight = (const float*)d_in[1];   // [1024, 4096] fp32
    float* out = (float*)d_out;                    // [11955, 1024] fp32
    (void)in_sizes; (void)n_in; (void)out_size;

    cudaFuncSetAttribute(merger_gemm, cudaFuncAttributeMaxDynamicSharedMemorySize, SMEM_DYN);
    convert_feat_kernel<<<23910, 256>>>(feat);     // 23910*256*8 = 48,967,680 elems exact
    reorder_w_kernel<<<4096, 256>>>(weight);
    merger_gemm<<<dim3(8, 94), 128, SMEM_DYN>>>(out);
}